// round 14
// baseline (speedup 1.0000x reference)
#include <cuda_runtime.h>
#include <cuda_bf16.h>
#include <cstdint>

#define B_   32
#define C_   768
#define HW_  1024
#define NTILES 1536          // 12 cb x 32 b x 4 hw-subtiles
#define NSTATS (32 * 12 * 192)

// -------- device scratch (allocation-free) --------
__device__ __nv_bfloat16 g_Xn[B_ * C_ * HW_];     // normalized X, bf16
__device__ __nv_bfloat16 g_Wb[2 * C_ * C_];       // interleaved bf16 weights
__device__ int           g_ctr;                   // persistent tile counter
__device__ float         g_stats[NSTATS];         // [b][cb][64ch][3] kv/kk/vv
__device__ int           g_done[32 * 12];         // subtiles finished per (b,cb)

// -------- GEMM tiling: M=128, N-chunk=64, K-stage=128, 4 chunks per tile -----
#define NSTG   6             // K stages of 128 per n-chunk
#define TCHUNK 4             // hw chunks per tile
#define NGS_T  (NSTG * TCHUNK)   // 24 stages per tile

#define SMEM_A_BYTES  (128 * 768 * 2)                // 196608
#define SMEM_B_OFF    SMEM_A_BYTES
#define SLOT_BYTES    (128 * 64 * 2)                 // 16384 per stage
#define SMEM_S_OFF    (SMEM_B_OFF + 2 * SLOT_BYTES)  // 229376
#define SMEM_G_TOTAL  (SMEM_S_OFF + 1088)            // 230464

// norm kernel smem
#define SMEM_N_TOTAL  (768 * 64 * 2 + 1024 * 4)      // 102400 -> 2 blocks/SM

// -------- PTX helpers --------
__device__ __forceinline__ void cp16(uint32_t dst, const void* src) {
    asm volatile("cp.async.cg.shared.global [%0], [%1], 16;\n" :: "r"(dst), "l"(src) : "memory");
}
#define CP_COMMIT() asm volatile("cp.async.commit_group;\n" ::: "memory")
#define CP_WAIT(n)  asm volatile("cp.async.wait_group %0;\n" :: "n"(n) : "memory")

// ---------------------------------------------------------------------------
// Kernel 1: fused one-pass RMSNorm (blocks 0..511) + weight prep (512..543).
// Also zeroes g_ctr / g_stats / g_done for the persistent GEMM.
// ---------------------------------------------------------------------------
__global__ void __launch_bounds__(1024, 2)
norm_wprep_kernel(const float* __restrict__ X, const float* __restrict__ Win) {
    extern __shared__ char smn[];
    const int bid = blockIdx.x;
    const int t = threadIdx.x;

    if (bid == 0 && t == 0) g_ctr = 0;
    {   // zero stats + done flags (each thread <= 1 element)
        int i = bid * 1024 + t;
        if (i < NSTATS) g_stats[i] = 0.f;
        if (bid == 1 && t < 32 * 12) g_done[t] = 0;
    }

    if (bid < 512) {
        __nv_bfloat16* cache = (__nv_bfloat16*)smn;          // [768*64]
        float* red = (float*)(smn + 768 * 64 * 2);           // [1024]
        const int b = bid >> 4;
        const int hwb = (bid & 15) * 64;
        const int hw = t & 63;
        const int qc = t >> 6;
        const int c0 = qc * 48;

        const float* xp = X + ((size_t)b * C_ + c0) * HW_ + hwb + hw;
        float s = 0.f;
#pragma unroll 8
        for (int c = 0; c < 48; c++) {
            float v = xp[c * HW_];
            cache[(c0 + c) * 64 + hw] = __float2bfloat16(v);
            s = fmaf(v, v, s);
        }
        red[t] = s;
        __syncthreads();
        float tot = 0.f;
#pragma unroll
        for (int k = 0; k < 16; k++) tot += red[k * 64 + hw];
        float inv = rsqrtf(tot * (1.0f / C_) + 1e-6f);

        __nv_bfloat16* op = g_Xn + ((size_t)b * C_ + c0) * HW_ + hwb + hw;
#pragma unroll 8
        for (int c = 0; c < 48; c++)
            op[c * HW_] = __float2bfloat16(
                __bfloat162float(cache[(c0 + c) * 64 + hw]) * inv);
    } else {
        // g_Wb row (cb*128 + a): g=a/16, r=a%16;
        // r<8 -> Wk[cb*64+g*8+r], else Wv[cb*64+g*8+(r-8)]
        const int base = (bid - 512) * 9216;
#pragma unroll
        for (int k = 0; k < 9; k++) {
            int i4 = base + k * 1024 + t;
            int row = i4 / 192;
            int kc = (i4 - row * 192) * 4;
            int cb = row >> 7, a = row & 127;
            int g = a >> 4, r = a & 15;
            int wrow = (r < 8) ? (cb * 64 + g * 8 + r)
                               : (C_ + cb * 64 + g * 8 + (r - 8));
            float4 v = *(const float4*)(Win + (size_t)wrow * C_ + kc);
            __nv_bfloat162 p0 = __floats2bfloat162_rn(v.x, v.y);
            __nv_bfloat162 p1 = __floats2bfloat162_rn(v.z, v.w);
            uint2 o;
            o.x = *(uint32_t*)&p0;
            o.y = *(uint32_t*)&p1;
            *(uint2*)(g_Wb + (size_t)row * C_ + kc) = o;
        }
    }
}

// ---------------------------------------------------------------------------
// Kernel 2: PERSISTENT fused KV-GEMM + gate + scaling, hw-split tiles.
// 1536 tiles: cb-major, then b, then h (4 hw-subtiles of 4 chunks each).
// Stats accumulated via global fp32 atomics; 4th finisher does the epilogue.
// ---------------------------------------------------------------------------
__global__ void __launch_bounds__(256, 1)
attn_gemm_kernel(const float* __restrict__ X, float* __restrict__ out) {
    extern __shared__ char smem[];
    const uint32_t sb = (uint32_t)__cvta_generic_to_shared(smem);
    float* sS = (float*)(smem + SMEM_S_OFF);       // [64][3]
    float* sGate = sS + 192;                       // [64]
    int*   sTile = (int*)(sGate + 64);
    int*   sDone = sTile + 1;

    const int tid = threadIdx.x;
    const int warp = tid >> 5, lane = tid & 31;
    const int wm = warp >> 1, wn = warp & 1;
    const int l_krow = tid >> 3;
    const int l_n16  = tid & 7;

    const int a_row_base = wm * 32 + (lane & 15);
    const int a_c16_lo   = (lane >> 4);
    const int b_kr_lane  = (lane & 15);
    const int b_n16_base = wn * 4 + (lane >> 4);

    int my_cb = -1;

    for (;;) {
        __syncthreads();
        if (tid == 0) *sTile = atomicAdd(&g_ctr, 1);
        __syncthreads();
        const int t = *sTile;
        if (t >= NTILES) break;
        const int cb = t >> 7;              // 12
        const int rem = t & 127;
        const int b = rem >> 2;             // 32
        const int h = rem & 3;              // 4 hw-subtiles

        if (tid < 192) sS[tid] = 0.f;

        // ---- A panel reload only when cb changes ----
        if (cb != my_cb) {
            my_cb = cb;
            const __nv_bfloat16* wsrc = g_Wb + (size_t)cb * 128 * C_;
            for (int unit = tid; unit < 12288; unit += 256) {
                int row = unit / 96, c16 = unit - (unit / 96) * 96;
                uint32_t dst = sb + (uint32_t)(row * 1536 +
                    (((c16 & 7) ^ (row & 7)) << 4) + ((c16 >> 3) << 7));
                cp16(dst, wsrc + (size_t)row * C_ + c16 * 8);
            }
            CP_COMMIT();
        }

        const __nv_bfloat16* XnB = g_Xn + (size_t)b * C_ * HW_;

#define LOAD_B(gs_)                                                          \
    {                                                                        \
        int ch_ = h * TCHUNK + (gs_) / NSTG;                                 \
        int st_ = (gs_) % NSTG; int buf_ = (gs_) & 1;                        \
        const __nv_bfloat16* src_ =                                          \
            XnB + (size_t)(st_ * 128) * HW_ + ch_ * 64;                      \
        _Pragma("unroll")                                                    \
        for (int i_ = 0; i_ < 4; i_++) {                                     \
            int kr_ = l_krow + i_ * 32;                                      \
            cp16(sb + SMEM_B_OFF + buf_ * SLOT_BYTES + kr_ * 128 +           \
                     ((l_n16 ^ (kr_ & 7)) << 4),                             \
                 src_ + (size_t)kr_ * HW_ + l_n16 * 8);                      \
        }                                                                    \
        CP_COMMIT();                                                         \
    }

#define LD_FRAGS(kk_, st_, sBb_, af_, bf_)                                   \
    {                                                                        \
        _Pragma("unroll")                                                    \
        for (int mi = 0; mi < 2; mi++) {                                     \
            int row = a_row_base + mi * 16;                                  \
            int c16 = (st_) * 16 + (kk_) * 2 + a_c16_lo;                     \
            uint32_t addr = sb + (uint32_t)(row * 1536 +                     \
                (((c16 & 7) ^ (row & 7)) << 4) + ((c16 >> 3) << 7));         \
            asm volatile(                                                    \
                "ldmatrix.sync.aligned.m8n8.x4.shared.b16 {%0,%1,%2,%3}, [%4];" \
                : "=r"((af_)[mi][0]), "=r"((af_)[mi][1]),                    \
                  "=r"((af_)[mi][2]), "=r"((af_)[mi][3])                     \
                : "r"(addr));                                                \
        }                                                                    \
        _Pragma("unroll")                                                    \
        for (int nj = 0; nj < 2; nj++) {                                     \
            int krow = (kk_) * 16 + b_kr_lane;                               \
            int n16 = b_n16_base + nj * 2;                                   \
            uint32_t addr = (sBb_) + (uint32_t)(krow * 128 +                 \
                ((n16 ^ (krow & 7)) << 4));                                  \
            uint32_t r0, r1, r2, r3;                                         \
            asm volatile(                                                    \
                "ldmatrix.sync.aligned.m8n8.x4.trans.shared.b16 {%0,%1,%2,%3}, [%4];" \
                : "=r"(r0), "=r"(r1), "=r"(r2), "=r"(r3)                     \
                : "r"(addr));                                                \
            (bf_)[nj * 2 + 0][0] = r0; (bf_)[nj * 2 + 0][1] = r1;            \
            (bf_)[nj * 2 + 1][0] = r2; (bf_)[nj * 2 + 1][1] = r3;            \
        }                                                                    \
    }

#define MMA8(af_, bf_)                                                       \
    {                                                                        \
        _Pragma("unroll")                                                    \
        for (int mi = 0; mi < 2; mi++)                                       \
            _Pragma("unroll")                                                \
            for (int ni = 0; ni < 4; ni++) {                                 \
                asm volatile(                                                \
                    "mma.sync.aligned.m16n8k16.row.col.f32.bf16.bf16.f32 "   \
                    "{%0,%1,%2,%3}, {%4,%5,%6,%7}, {%8,%9}, {%0,%1,%2,%3};"  \
                    : "+f"(acc[mi][ni][0]), "+f"(acc[mi][ni][1]),            \
                      "+f"(acc[mi][ni][2]), "+f"(acc[mi][ni][3])             \
                    : "r"((af_)[mi][0]), "r"((af_)[mi][1]),                  \
                      "r"((af_)[mi][2]), "r"((af_)[mi][3]),                  \
                      "r"((bf_)[ni][0]), "r"((bf_)[ni][1]));                 \
            }                                                                \
    }

        LOAD_B(0);

        float skv[2] = {0.f, 0.f}, skk[2] = {0.f, 0.f}, svv[2] = {0.f, 0.f};
        float acc[2][4][4];
        uint32_t afA[2][4], afB[2][4];
        uint32_t bfA[4][2], bfB[4][2];

#pragma unroll 1
        for (int gs = 0; gs < NGS_T; gs++) {
            const int st = gs % NSTG;

            CP_WAIT(0);
            __syncthreads();
            if (gs + 1 < NGS_T) LOAD_B(gs + 1);

            if (st == 0) {
#pragma unroll
                for (int mi = 0; mi < 2; mi++)
#pragma unroll
                    for (int ni = 0; ni < 4; ni++)
#pragma unroll
                        for (int q = 0; q < 4; q++) acc[mi][ni][q] = 0.f;
            }

            const uint32_t sBb = sb + SMEM_B_OFF + (gs & 1) * SLOT_BYTES;

            LD_FRAGS(0, st, sBb, afA, bfA);
            LD_FRAGS(1, st, sBb, afB, bfB);
            MMA8(afA, bfA);
            LD_FRAGS(2, st, sBb, afA, bfA);
            MMA8(afB, bfB);
            LD_FRAGS(3, st, sBb, afB, bfB);
            MMA8(afA, bfA);
            LD_FRAGS(4, st, sBb, afA, bfA);
            MMA8(afB, bfB);
            LD_FRAGS(5, st, sBb, afB, bfB);
            MMA8(afA, bfA);
            LD_FRAGS(6, st, sBb, afA, bfA);
            MMA8(afB, bfB);
            LD_FRAGS(7, st, sBb, afB, bfB);
            MMA8(afA, bfA);
            MMA8(afB, bfB);

            if (st == NSTG - 1) {
#pragma unroll
                for (int mi = 0; mi < 2; mi++)
#pragma unroll
                    for (int ni = 0; ni < 4; ni++) {
                        float k0 = acc[mi][ni][0], k1 = acc[mi][ni][1];
                        float v0 = acc[mi][ni][2], v1 = acc[mi][ni][3];
                        skv[mi] += k0 * v0 + k1 * v1;
                        skk[mi] += k0 * k0 + k1 * k1;
                        svv[mi] += v0 * v0 + v1 * v1;
                    }
            }
        }
#undef LOAD_B
#undef LD_FRAGS
#undef MMA8

        // quad reduce -> smem stats
#pragma unroll
        for (int mi = 0; mi < 2; mi++) {
            skv[mi] += __shfl_down_sync(0xffffffffu, skv[mi], 1);
            skv[mi] += __shfl_down_sync(0xffffffffu, skv[mi], 2);
            skk[mi] += __shfl_down_sync(0xffffffffu, skk[mi], 1);
            skk[mi] += __shfl_down_sync(0xffffffffu, skk[mi], 2);
            svv[mi] += __shfl_down_sync(0xffffffffu, svv[mi], 1);
            svv[mi] += __shfl_down_sync(0xffffffffu, svv[mi], 2);
        }
        __syncthreads();
        if ((lane & 3) == 0) {
#pragma unroll
            for (int mi = 0; mi < 2; mi++) {
                int chl = (wm * 2 + mi) * 8 + (lane >> 2);
                atomicAdd(&sS[chl * 3 + 0], skv[mi]);
                atomicAdd(&sS[chl * 3 + 1], skk[mi]);
                atomicAdd(&sS[chl * 3 + 2], svv[mi]);
            }
        }
        __syncthreads();

        // accumulate partial stats to global; last of 4 subtiles does epilogue
        const int tg = b * 12 + cb;
        const int sbase = tg * 192;
        if (tid < 192) atomicAdd(&g_stats[sbase + tid], sS[tid]);
        __threadfence();
        if (tid == 0) *sDone = atomicAdd(&g_done[tg], 1);
        __syncthreads();

        if (*sDone == 3) {
            __threadfence();
            if (tid < 64) {
                float kv  = __ldcg(&g_stats[sbase + tid * 3 + 0]);
                float kk2 = __ldcg(&g_stats[sbase + tid * 3 + 1]);
                float vv2 = __ldcg(&g_stats[sbase + tid * 3 + 2]);
                float cosv = kv / ((sqrtf(kk2) + 1e-12f) * (sqrtf(vv2) + 1e-12f));
                sGate[tid] = 0.5f * cosv + 0.5f;
            }
            __syncthreads();

            const float4* X4 = (const float4*)X;
            float4* O4 = (float4*)out;
            const size_t base4 = ((size_t)b * C_ + cb * 64) * (HW_ / 4);
#pragma unroll 4
            for (int i = tid; i < 64 * 256; i += 256) {
                int row = i >> 8;
                float a = sGate[row];
                float4 x = X4[base4 + i];
                float4 o;
                o.x = a * x.x; o.y = a * x.y; o.z = a * x.z; o.w = a * x.w;
                O4[base4 + i] = o;
            }
        }
    }
}

// ---------------------------------------------------------------------------
extern "C" void kernel_launch(void* const* d_in, const int* in_sizes, int n_in,
                              void* d_out, int out_size) {
    const float* X = (const float*)d_in[0];
    const float* W = (const float*)d_in[1];
    float* out = (float*)d_out;

    cudaFuncSetAttribute(norm_wprep_kernel,
                         cudaFuncAttributeMaxDynamicSharedMemorySize, SMEM_N_TOTAL);
    cudaFuncSetAttribute(attn_gemm_kernel,
                         cudaFuncAttributeMaxDynamicSharedMemorySize, SMEM_G_TOTAL);

    norm_wprep_kernel<<<544, 1024, SMEM_N_TOTAL>>>(X, W);
    attn_gemm_kernel<<<152, 256, SMEM_G_TOTAL>>>(X, out);
}

// round 17
// speedup vs baseline: 1.0003x; 1.0003x over previous
#include <cuda_runtime.h>
#include <cuda_bf16.h>
#include <cstdint>

#define B_   32
#define C_   768
#define HW_  1024
#define NTILES 1536          // 12 cb x 32 b x 4 hw-subtiles
#define NSTATS (32 * 12 * 192)

// -------- device scratch (allocation-free) --------
__device__ __nv_bfloat16 g_Xn[B_ * C_ * HW_];     // normalized X, bf16
__device__ __nv_bfloat16 g_Wb[2 * C_ * C_];       // interleaved bf16 weights
__device__ int           g_ctr;                   // persistent tile counter
__device__ float         g_stats[NSTATS];         // [b][cb][64ch][3] kv/kk/vv
__device__ int           g_done[32 * 12];         // subtiles finished per (b,cb)

// -------- GEMM tiling: M=128, N-chunk=64, K-stage=128, 4 chunks per tile -----
#define NSTG   6
#define TCHUNK 4
#define NGS_T  (NSTG * TCHUNK)   // 24 stages per tile

#define SMEM_A_BYTES  (128 * 768 * 2)                // 196608
#define SMEM_B_OFF    SMEM_A_BYTES
#define SLOT_BYTES    (128 * 64 * 2)                 // 16384 per stage
#define SMEM_S_OFF    (SMEM_B_OFF + 2 * SLOT_BYTES)  // 229376
#define SMEM_G_TOTAL  (SMEM_S_OFF + 1088)            // 230464

// norm kernel smem: bf16 cache [768*32] + fp32 reduce [256]
#define SMEM_N_TOTAL  (768 * 32 * 2 + 256 * 4)       // 50176 -> occ 4

// -------- PTX helpers --------
__device__ __forceinline__ void cp16(uint32_t dst, const void* src) {
    asm volatile("cp.async.cg.shared.global [%0], [%1], 16;\n" :: "r"(dst), "l"(src) : "memory");
}
#define CP_COMMIT() asm volatile("cp.async.commit_group;\n" ::: "memory")
#define CP_WAIT(n)  asm volatile("cp.async.wait_group %0;\n" :: "n"(n) : "memory")

// ---------------------------------------------------------------------------
// Kernel 1: one-pass RMSNorm, 256-thread blocks (units of 32 hw), occ 4.
// blocks 0..1023 = norm units; 1024..1055 = weight prep. Zeroes counters.
// ---------------------------------------------------------------------------
__global__ void __launch_bounds__(256, 4)
norm_wprep_kernel(const float* __restrict__ X, const float* __restrict__ Win) {
    extern __shared__ char smn[];
    const int bid = blockIdx.x;
    const int t = threadIdx.x;

    if (bid == 0 && t == 0) g_ctr = 0;
    {
        int zi = bid * 256 + t;
        if (zi < NSTATS) g_stats[zi] = 0.f;
        if (zi < 32 * 12) g_done[zi] = 0;
    }

    if (bid < 1024) {
        __nv_bfloat16* cache = (__nv_bfloat16*)smn;          // [768*32]
        float* red = (float*)(smn + 768 * 32 * 2);           // [256]
        const int b = bid >> 5;
        const int hwb = (bid & 31) * 32;
        const int hw = t & 31;
        const int q  = t >> 5;           // 0..7, 96 channels each
        const int c0 = q * 96;

        const float* xp = X + ((size_t)b * C_ + c0) * HW_ + hwb + hw;
        float s = 0.f;
#pragma unroll 8
        for (int c = 0; c < 96; c++) {
            float v = xp[c * HW_];
            cache[(c0 + c) * 32 + hw] = __float2bfloat16(v);
            s = fmaf(v, v, s);
        }
        red[t] = s;
        __syncthreads();
        float tot = 0.f;
#pragma unroll
        for (int k = 0; k < 8; k++) tot += red[k * 32 + hw];
        float inv = rsqrtf(tot * (1.0f / C_) + 1e-6f);

        __nv_bfloat16* op = g_Xn + ((size_t)b * C_ + c0) * HW_ + hwb + hw;
#pragma unroll 8
        for (int c = 0; c < 96; c++)
            op[c * HW_] = __float2bfloat16(
                __bfloat162float(cache[(c0 + c) * 32 + hw]) * inv);
    } else {
        // g_Wb row (cb*128 + a): g=a/16, r=a%16;
        // r<8 -> Wk[cb*64+g*8+r], else Wv[cb*64+g*8+(r-8)]
        const int base = (bid - 1024) * 9216;
#pragma unroll 4
        for (int k = 0; k < 36; k++) {
            int i4 = base + k * 256 + t;
            int row = i4 / 192;
            int kc = (i4 - row * 192) * 4;
            int cb = row >> 7, a = row & 127;
            int g = a >> 4, r = a & 15;
            int wrow = (r < 8) ? (cb * 64 + g * 8 + r)
                               : (C_ + cb * 64 + g * 8 + (r - 8));
            float4 v = *(const float4*)(Win + (size_t)wrow * C_ + kc);
            __nv_bfloat162 p0 = __floats2bfloat162_rn(v.x, v.y);
            __nv_bfloat162 p1 = __floats2bfloat162_rn(v.z, v.w);
            uint2 o;
            o.x = *(uint32_t*)&p0;
            o.y = *(uint32_t*)&p1;
            *(uint2*)(g_Wb + (size_t)row * C_ + kc) = o;
        }
    }
}

// ---------------------------------------------------------------------------
// Kernel 2: PERSISTENT fused KV-GEMM + gate + scaling, hw-split tiles,
// with CROSS-TILE B prefetch (next tile's first stage issued before the
// current tile's last compute + epilogue).
// ---------------------------------------------------------------------------
__global__ void __launch_bounds__(256, 1)
attn_gemm_kernel(const float* __restrict__ X, float* __restrict__ out) {
    extern __shared__ char smem[];
    const uint32_t sb = (uint32_t)__cvta_generic_to_shared(smem);
    float* sS = (float*)(smem + SMEM_S_OFF);       // [64][3]
    float* sGate = sS + 192;                       // [64]
    int*   sTile = (int*)(sGate + 64);
    int*   sDone = sTile + 1;

    const int tid = threadIdx.x;
    const int warp = tid >> 5, lane = tid & 31;
    const int wm = warp >> 1, wn = warp & 1;
    const int l_krow = tid >> 3;
    const int l_n16  = tid & 7;

    const int a_row_base = wm * 32 + (lane & 15);
    const int a_c16_lo   = (lane >> 4);
    const int b_kr_lane  = (lane & 15);
    const int b_n16_base = wn * 4 + (lane >> 4);

#define LOAD_A(cb_)                                                          \
    {                                                                        \
        const __nv_bfloat16* wsrc = g_Wb + (size_t)(cb_) * 128 * C_;         \
        for (int unit = tid; unit < 12288; unit += 256) {                    \
            int row = unit / 96, c16 = unit - (unit / 96) * 96;              \
            uint32_t dst = sb + (uint32_t)(row * 1536 +                      \
                (((c16 & 7) ^ (row & 7)) << 4) + ((c16 >> 3) << 7));         \
            cp16(dst, wsrc + (size_t)row * C_ + c16 * 8);                    \
        }                                                                    \
        CP_COMMIT();                                                         \
    }

#define LOAD_BG(XnB_, h_, gs_)                                               \
    {                                                                        \
        int ch_ = (h_) * TCHUNK + (gs_) / NSTG;                              \
        int st_ = (gs_) % NSTG; int buf_ = (gs_) & 1;                        \
        const __nv_bfloat16* src_ =                                          \
            (XnB_) + (size_t)(st_ * 128) * HW_ + ch_ * 64;                   \
        _Pragma("unroll")                                                    \
        for (int i_ = 0; i_ < 4; i_++) {                                     \
            int kr_ = l_krow + i_ * 32;                                      \
            cp16(sb + SMEM_B_OFF + buf_ * SLOT_BYTES + kr_ * 128 +           \
                     ((l_n16 ^ (kr_ & 7)) << 4),                             \
                 src_ + (size_t)kr_ * HW_ + l_n16 * 8);                      \
        }                                                                    \
        CP_COMMIT();                                                         \
    }

#define LD_FRAGS(kk_, st_, sBb_, af_, bf_)                                   \
    {                                                                        \
        _Pragma("unroll")                                                    \
        for (int mi = 0; mi < 2; mi++) {                                     \
            int row = a_row_base + mi * 16;                                  \
            int c16 = (st_) * 16 + (kk_) * 2 + a_c16_lo;                     \
            uint32_t addr = sb + (uint32_t)(row * 1536 +                     \
                (((c16 & 7) ^ (row & 7)) << 4) + ((c16 >> 3) << 7));         \
            asm volatile(                                                    \
                "ldmatrix.sync.aligned.m8n8.x4.shared.b16 {%0,%1,%2,%3}, [%4];" \
                : "=r"((af_)[mi][0]), "=r"((af_)[mi][1]),                    \
                  "=r"((af_)[mi][2]), "=r"((af_)[mi][3])                     \
                : "r"(addr));                                                \
        }                                                                    \
        _Pragma("unroll")                                                    \
        for (int nj = 0; nj < 2; nj++) {                                     \
            int krow = (kk_) * 16 + b_kr_lane;                               \
            int n16 = b_n16_base + nj * 2;                                   \
            uint32_t addr = (sBb_) + (uint32_t)(krow * 128 +                 \
                ((n16 ^ (krow & 7)) << 4));                                  \
            uint32_t r0, r1, r2, r3;                                         \
            asm volatile(                                                    \
                "ldmatrix.sync.aligned.m8n8.x4.trans.shared.b16 {%0,%1,%2,%3}, [%4];" \
                : "=r"(r0), "=r"(r1), "=r"(r2), "=r"(r3)                     \
                : "r"(addr));                                                \
            (bf_)[nj * 2 + 0][0] = r0; (bf_)[nj * 2 + 0][1] = r1;            \
            (bf_)[nj * 2 + 1][0] = r2; (bf_)[nj * 2 + 1][1] = r3;            \
        }                                                                    \
    }

#define MMA8(af_, bf_)                                                       \
    {                                                                        \
        _Pragma("unroll")                                                    \
        for (int mi = 0; mi < 2; mi++)                                       \
            _Pragma("unroll")                                                \
            for (int ni = 0; ni < 4; ni++) {                                 \
                asm volatile(                                                \
                    "mma.sync.aligned.m16n8k16.row.col.f32.bf16.bf16.f32 "   \
                    "{%0,%1,%2,%3}, {%4,%5,%6,%7}, {%8,%9}, {%0,%1,%2,%3};"  \
                    : "+f"(acc[mi][ni][0]), "+f"(acc[mi][ni][1]),            \
                      "+f"(acc[mi][ni][2]), "+f"(acc[mi][ni][3])             \
                    : "r"((af_)[mi][0]), "r"((af_)[mi][1]),                  \
                      "r"((af_)[mi][2]), "r"((af_)[mi][3]),                  \
                      "r"((bf_)[ni][0]), "r"((bf_)[ni][1]));                 \
            }                                                                \
    }

    // ---- prologue: claim first tile, load its A panel + first B stage ----
    if (tid == 0) *sTile = atomicAdd(&g_ctr, 1);
    __syncthreads();
    int t = *sTile;
    if (t >= NTILES) return;

    int cb = t >> 7, rem = t & 127, b = rem >> 2, h = rem & 3;
    int my_cb = cb;
    LOAD_A(cb);
    const __nv_bfloat16* XnB = g_Xn + (size_t)b * C_ * HW_;
    LOAD_BG(XnB, h, 0);

    for (;;) {
        __syncthreads();
        if (tid < 192) sS[tid] = 0.f;

        float skv[2] = {0.f, 0.f}, skk[2] = {0.f, 0.f}, svv[2] = {0.f, 0.f};
        float acc[2][4][4];
        uint32_t afA[2][4], afB[2][4];
        uint32_t bfA[4][2], bfB[4][2];
        int nextT = NTILES;

#pragma unroll 1
        for (int gs = 0; gs < NGS_T; gs++) {
            const int st = gs % NSTG;

            CP_WAIT(0);
            __syncthreads();

            if (gs == NGS_T - 2) {
                if (tid == 0) *sTile = atomicAdd(&g_ctr, 1);
                LOAD_BG(XnB, h, gs + 1);
            } else if (gs < NGS_T - 1) {
                LOAD_BG(XnB, h, gs + 1);
            } else {
                // last stage: prefetch NEXT tile's first B stage (buf 0)
                nextT = *sTile;          // published by this stage's barrier
                if (nextT < NTILES) {
                    int nrem = nextT & 127;
                    const __nv_bfloat16* XnN =
                        g_Xn + (size_t)(nrem >> 2) * C_ * HW_;
                    LOAD_BG(XnN, (nrem & 3), 0);
                }
            }

            if (st == 0) {
#pragma unroll
                for (int mi = 0; mi < 2; mi++)
#pragma unroll
                    for (int ni = 0; ni < 4; ni++)
#pragma unroll
                        for (int q = 0; q < 4; q++) acc[mi][ni][q] = 0.f;
            }

            const uint32_t sBb = sb + SMEM_B_OFF + (gs & 1) * SLOT_BYTES;

            LD_FRAGS(0, st, sBb, afA, bfA);
            LD_FRAGS(1, st, sBb, afB, bfB);
            MMA8(afA, bfA);
            LD_FRAGS(2, st, sBb, afA, bfA);
            MMA8(afB, bfB);
            LD_FRAGS(3, st, sBb, afB, bfB);
            MMA8(afA, bfA);
            LD_FRAGS(4, st, sBb, afA, bfA);
            MMA8(afB, bfB);
            LD_FRAGS(5, st, sBb, afB, bfB);
            MMA8(afA, bfA);
            LD_FRAGS(6, st, sBb, afA, bfA);
            MMA8(afB, bfB);
            LD_FRAGS(7, st, sBb, afB, bfB);
            MMA8(afA, bfA);
            MMA8(afB, bfB);

            if (st == NSTG - 1) {
#pragma unroll
                for (int mi = 0; mi < 2; mi++)
#pragma unroll
                    for (int ni = 0; ni < 4; ni++) {
                        float k0 = acc[mi][ni][0], k1 = acc[mi][ni][1];
                        float v0 = acc[mi][ni][2], v1 = acc[mi][ni][3];
                        skv[mi] += k0 * v0 + k1 * v1;
                        skk[mi] += k0 * k0 + k1 * k1;
                        svv[mi] += v0 * v0 + v1 * v1;
                    }
            }
        }

        // ---- epilogue (next tile's B already in flight) ----
#pragma unroll
        for (int mi = 0; mi < 2; mi++) {
            skv[mi] += __shfl_down_sync(0xffffffffu, skv[mi], 1);
            skv[mi] += __shfl_down_sync(0xffffffffu, skv[mi], 2);
            skk[mi] += __shfl_down_sync(0xffffffffu, skk[mi], 1);
            skk[mi] += __shfl_down_sync(0xffffffffu, skk[mi], 2);
            svv[mi] += __shfl_down_sync(0xffffffffu, svv[mi], 1);
            svv[mi] += __shfl_down_sync(0xffffffffu, svv[mi], 2);
        }
        __syncthreads();
        if ((lane & 3) == 0) {
#pragma unroll
            for (int mi = 0; mi < 2; mi++) {
                int chl = (wm * 2 + mi) * 8 + (lane >> 2);
                atomicAdd(&sS[chl * 3 + 0], skv[mi]);
                atomicAdd(&sS[chl * 3 + 1], skk[mi]);
                atomicAdd(&sS[chl * 3 + 2], svv[mi]);
            }
        }
        __syncthreads();

        const int tg = b * 12 + cb;
        const int sbase = tg * 192;
        if (tid < 192) atomicAdd(&g_stats[sbase + tid], sS[tid]);
        __threadfence();
        if (tid == 0) *sDone = atomicAdd(&g_done[tg], 1);
        __syncthreads();

        if (*sDone == 3) {
            __threadfence();
            if (tid < 64) {
                float kv  = __ldcg(&g_stats[sbase + tid * 3 + 0]);
                float kk2 = __ldcg(&g_stats[sbase + tid * 3 + 1]);
                float vv2 = __ldcg(&g_stats[sbase + tid * 3 + 2]);
                float cosv = kv / ((sqrtf(kk2) + 1e-12f) * (sqrtf(vv2) + 1e-12f));
                sGate[tid] = 0.5f * cosv + 0.5f;
            }
            __syncthreads();

            const float4* X4 = (const float4*)X;
            float4* O4 = (float4*)out;
            const size_t base4 = ((size_t)b * C_ + cb * 64) * (HW_ / 4);
#pragma unroll 4
            for (int i = tid; i < 64 * 256; i += 256) {
                int row = i >> 8;
                float a = sGate[row];
                float4 x = X4[base4 + i];
                float4 o;
                o.x = a * x.x; o.y = a * x.y; o.z = a * x.z; o.w = a * x.w;
                O4[base4 + i] = o;
            }
        }

        if (nextT >= NTILES) break;
        cb = nextT >> 7; rem = nextT & 127; b = rem >> 2; h = rem & 3;
        XnB = g_Xn + (size_t)b * C_ * HW_;
        if (cb != my_cb) {      // A reload overlaps next tile's B latency
            my_cb = cb;
            LOAD_A(cb);
        }
        t = nextT;
    }
#undef LOAD_A
#undef LOAD_BG
#undef LD_FRAGS
#undef MMA8
}

// ---------------------------------------------------------------------------
extern "C" void kernel_launch(void* const* d_in, const int* in_sizes, int n_in,
                              void* d_out, int out_size) {
    const float* X = (const float*)d_in[0];
    const float* W = (const float*)d_in[1];
    float* out = (float*)d_out;

    cudaFuncSetAttribute(norm_wprep_kernel,
                         cudaFuncAttributeMaxDynamicSharedMemorySize, SMEM_N_TOTAL);
    cudaFuncSetAttribute(attn_gemm_kernel,
                         cudaFuncAttributeMaxDynamicSharedMemorySize, SMEM_G_TOTAL);

    norm_wprep_kernel<<<1056, 256, SMEM_N_TOTAL>>>(X, W);
    attn_gemm_kernel<<<152, 256, SMEM_G_TOTAL>>>(X, out);
}